// round 11
// baseline (speedup 1.0000x reference)
#include <cuda_runtime.h>

// TripletLoss with per-class margins — single fused kernel.
//   d_ap = ||a - p + 1e-6||_2, d_an = ||a - n + 1e-6||_2  (eps per element)
//   out  = mean(max(d_ap - d_an + margins[c], 0))
//
// Layout: 8 lanes per row, 4 rows per warp per iteration.
//   - 12 front-batched LDG.128 per lane (4 per tensor), default cache policy
//     (experiment: .cs evict-first removed; only change vs R9 @ 63.6us)
//   - strided lane assignment keeps every LDG = 4 full 128B lines per warp
//   - one 3-stage butterfly (offs 4,2,1) reduces all 4 rows at once
// Grid = one occupancy wave via the occupancy API (host-side, allocation-free,
// graph-capture-safe). cs dtype int64 demoted to int32 by JAX; probed in-kernel.

#define EPS 1e-6f
#define D 128

__constant__ float c_margins[4] = {0.1f, 0.085f, 0.07f, 0.04f};

__device__ double g_sum = 0.0;
__device__ unsigned int g_count = 0u;

__global__ void __launch_bounds__(256) triplet_fused_kernel(
    const float* __restrict__ a,
    const float* __restrict__ p,
    const float* __restrict__ n,
    const int* __restrict__ cs32,
    float* __restrict__ out,
    int B, float inv_b)
{
    const int lane = threadIdx.x & 31;
    const int warp = threadIdx.x >> 5;
    const int warps_per_block = blockDim.x >> 5;
    const int gwarp = blockIdx.x * warps_per_block + warp;
    const int nwarps = gridDim.x * warps_per_block;

    const int grp = lane >> 3;   // which of 4 rows this lane works on
    const int sub = lane & 7;    // position within the 8-lane row group

    // ---- In-kernel cs layout probe ----
    // int64 LE with values 0..3 => every odd int32 word == 0.
    // int32 => odd words nonzero w.p. 3/4 each. 256 samples: certain.
    int probe = 0;
    {
        const int limit = (B < 4096) ? B : 4096;
        const int i = 1 + 2 * (int)threadIdx.x;
        if (i < limit) probe = (cs32[i] != 0);
    }
    const int cstride = __syncthreads_or(probe) ? 1 : 2;

    float local = 0.0f;

    int rowbase = gwarp * 4;
    const int stride = nwarps * 4;

    for (; rowbase < B; rowbase += stride) {
        const int myrow = rowbase + grp;
        const bool valid = (myrow < B);
        const size_t rbase = (size_t)(valid ? myrow : 0) * D;
        const float* arow = a + rbase + sub * 4;
        const float* prow = p + rbase + sub * 4;
        const float* nrow = n + rbase + sub * 4;

        // 12 front-batched LDG.128 (default policy). LDG k: lane sub reads
        // floats [k*32 + sub*4 .. +4) -> 4 rows x 1 full 128B line per warp.
        float4 av0 = *reinterpret_cast<const float4*>(arow + 0 * 32);
        float4 av1 = *reinterpret_cast<const float4*>(arow + 1 * 32);
        float4 av2 = *reinterpret_cast<const float4*>(arow + 2 * 32);
        float4 av3 = *reinterpret_cast<const float4*>(arow + 3 * 32);
        float4 pv0 = *reinterpret_cast<const float4*>(prow + 0 * 32);
        float4 pv1 = *reinterpret_cast<const float4*>(prow + 1 * 32);
        float4 pv2 = *reinterpret_cast<const float4*>(prow + 2 * 32);
        float4 pv3 = *reinterpret_cast<const float4*>(prow + 3 * 32);
        float4 nv0 = *reinterpret_cast<const float4*>(nrow + 0 * 32);
        float4 nv1 = *reinterpret_cast<const float4*>(nrow + 1 * 32);
        float4 nv2 = *reinterpret_cast<const float4*>(nrow + 2 * 32);
        float4 nv3 = *reinterpret_cast<const float4*>(nrow + 3 * 32);

        float sap, san, d;
        d = av0.x - pv0.x + EPS; sap = d * d;
        d = av0.y - pv0.y + EPS; sap = fmaf(d, d, sap);
        d = av0.z - pv0.z + EPS; sap = fmaf(d, d, sap);
        d = av0.w - pv0.w + EPS; sap = fmaf(d, d, sap);
        d = av1.x - pv1.x + EPS; sap = fmaf(d, d, sap);
        d = av1.y - pv1.y + EPS; sap = fmaf(d, d, sap);
        d = av1.z - pv1.z + EPS; sap = fmaf(d, d, sap);
        d = av1.w - pv1.w + EPS; sap = fmaf(d, d, sap);
        d = av2.x - pv2.x + EPS; sap = fmaf(d, d, sap);
        d = av2.y - pv2.y + EPS; sap = fmaf(d, d, sap);
        d = av2.z - pv2.z + EPS; sap = fmaf(d, d, sap);
        d = av2.w - pv2.w + EPS; sap = fmaf(d, d, sap);
        d = av3.x - pv3.x + EPS; sap = fmaf(d, d, sap);
        d = av3.y - pv3.y + EPS; sap = fmaf(d, d, sap);
        d = av3.z - pv3.z + EPS; sap = fmaf(d, d, sap);
        d = av3.w - pv3.w + EPS; sap = fmaf(d, d, sap);

        d = av0.x - nv0.x + EPS; san = d * d;
        d = av0.y - nv0.y + EPS; san = fmaf(d, d, san);
        d = av0.z - nv0.z + EPS; san = fmaf(d, d, san);
        d = av0.w - nv0.w + EPS; san = fmaf(d, d, san);
        d = av1.x - nv1.x + EPS; san = fmaf(d, d, san);
        d = av1.y - nv1.y + EPS; san = fmaf(d, d, san);
        d = av1.z - nv1.z + EPS; san = fmaf(d, d, san);
        d = av1.w - nv1.w + EPS; san = fmaf(d, d, san);
        d = av2.x - nv2.x + EPS; san = fmaf(d, d, san);
        d = av2.y - nv2.y + EPS; san = fmaf(d, d, san);
        d = av2.z - nv2.z + EPS; san = fmaf(d, d, san);
        d = av2.w - nv2.w + EPS; san = fmaf(d, d, san);
        d = av3.x - nv3.x + EPS; san = fmaf(d, d, san);
        d = av3.y - nv3.y + EPS; san = fmaf(d, d, san);
        d = av3.z - nv3.z + EPS; san = fmaf(d, d, san);
        d = av3.w - nv3.w + EPS; san = fmaf(d, d, san);

        // 3-stage butterfly within each 8-lane group: reduces all 4 rows.
        #pragma unroll
        for (int off = 4; off > 0; off >>= 1) {
            sap += __shfl_xor_sync(0xffffffffu, sap, off);
            san += __shfl_xor_sync(0xffffffffu, san, off);
        }

        if (sub == 0 && valid) {
            const int c = cs32[(size_t)myrow * cstride] & 3;
            local += fmaxf(sqrtf(sap) - sqrtf(san) + c_margins[c], 0.0f);
        }
    }

    // ---- Block reduce ----
    #pragma unroll
    for (int off = 16; off > 0; off >>= 1)
        local += __shfl_xor_sync(0xffffffffu, local, off);

    __shared__ float s_part[32];
    if (lane == 0) s_part[warp] = local;
    __syncthreads();

    if (warp == 0) {
        float v = (lane < warps_per_block) ? s_part[lane] : 0.0f;
        #pragma unroll
        for (int off = 16; off > 0; off >>= 1)
            v += __shfl_xor_sync(0xffffffffu, v, off);

        // ---- Fused epilogue: last block writes mean, resets state ----
        if (lane == 0) {
            atomicAdd(&g_sum, (double)v);
            __threadfence();
            const unsigned int old = atomicAdd(&g_count, 1u);
            if (old == gridDim.x - 1u) {
                const double s = atomicAdd(&g_sum, 0.0);  // ordered read
                *out = (float)(s * (double)inv_b);
                g_sum = 0.0;
                g_count = 0u;
                __threadfence();
            }
        }
    }
}

extern "C" void kernel_launch(void* const* d_in, const int* in_sizes, int n_in,
                              void* d_out, int out_size)
{
    const float* anchors = (const float*)d_in[0];
    const float* poss    = (const float*)d_in[1];
    const float* negs    = (const float*)d_in[2];
    const int*   cs32    = (const int*)d_in[3];
    float* out = (float*)d_out;

    const int B = in_sizes[3];
    const int threads = 256;

    // Exactly one occupancy wave: SMs x max-resident-CTAs for this kernel.
    // Host-side queries; no allocation; safe under graph capture. Cached so
    // the grid is identical across capture and replays.
    static int blocks = 0;
    if (blocks == 0) {
        int dev = 0, sms = 0, per_sm = 0;
        cudaGetDevice(&dev);
        cudaDeviceGetAttribute(&sms, cudaDevAttrMultiProcessorCount, dev);
        cudaOccupancyMaxActiveBlocksPerMultiprocessor(
            &per_sm, triplet_fused_kernel, threads, 0);
        if (sms <= 0) sms = 148;
        if (per_sm < 4) per_sm = 4;
        blocks = sms * per_sm;
    }

    triplet_fused_kernel<<<blocks, threads>>>(anchors, poss, negs, cs32, out,
                                              B, 1.0f / (float)B);
}

// round 15
// speedup vs baseline: 1.0255x; 1.0255x over previous
#include <cuda_runtime.h>

// TripletLoss with per-class margins — single fused kernel. FINAL-candidate:
// all measured configs (occ 46-94%, MLP 6-12, .cs vs default) pin at the
// path-independent ~6.35 TB/s LTS/HBM ceiling; 403MB/6.38TB/s = 63.2us floor,
// this config measured 63.6us. Locking in best-measured variant (.cs).
//
//   d_ap = ||a - p + 1e-6||_2, d_an = ||a - n + 1e-6||_2  (eps per element)
//   out  = mean(max(d_ap - d_an + margins[c], 0))
//
// Layout: 8 lanes per row, 4 rows per warp per iteration; 12 front-batched
// streaming LDG.128; 3-stage butterfly reduces 4 rows at once. Grid = one
// occupancy wave (host occupancy API; allocation-free; capture-safe).
// cs dtype int64 demoted to int32 by JAX; layout probed in-kernel.

#define EPS 1e-6f
#define D 128

__constant__ float c_margins[4] = {0.1f, 0.085f, 0.07f, 0.04f};

__device__ double g_sum = 0.0;
__device__ unsigned int g_count = 0u;

__global__ void __launch_bounds__(256) triplet_fused_kernel(
    const float* __restrict__ a,
    const float* __restrict__ p,
    const float* __restrict__ n,
    const int* __restrict__ cs32,
    float* __restrict__ out,
    int B, float inv_b)
{
    const int lane = threadIdx.x & 31;
    const int warp = threadIdx.x >> 5;
    const int warps_per_block = blockDim.x >> 5;
    const int gwarp = blockIdx.x * warps_per_block + warp;
    const int nwarps = gridDim.x * warps_per_block;

    const int grp = lane >> 3;   // which of 4 rows this lane works on
    const int sub = lane & 7;    // position within the 8-lane row group

    // ---- In-kernel cs layout probe ----
    // int64 LE with values 0..3 => every odd int32 word == 0.
    // int32 => odd words nonzero w.p. 3/4 each. 256 samples: certain.
    int probe = 0;
    {
        const int limit = (B < 4096) ? B : 4096;
        const int i = 1 + 2 * (int)threadIdx.x;
        if (i < limit) probe = (cs32[i] != 0);
    }
    const int cstride = __syncthreads_or(probe) ? 1 : 2;

    float local = 0.0f;

    const int stride = nwarps * 4;
    // Uniform region: all 4 rows of the group are in-bounds.
    const int Bmain = B & ~3;    // B multiple of 4 in practice; guard anyway

    int rowbase = gwarp * 4;
    for (; rowbase + 4 <= Bmain; rowbase += stride) {
        const int myrow = rowbase + grp;
        const size_t rbase = (size_t)myrow * D;
        const float* arow = a + rbase + sub * 4;
        const float* prow = p + rbase + sub * 4;
        const float* nrow = n + rbase + sub * 4;

        // 12 front-batched streaming LDG.128. LDG k: lane sub reads floats
        // [k*32 + sub*4 .. +4) -> warp covers 4 rows x 1 full 128B line each.
        float4 av0 = __ldcs(reinterpret_cast<const float4*>(arow + 0 * 32));
        float4 av1 = __ldcs(reinterpret_cast<const float4*>(arow + 1 * 32));
        float4 av2 = __ldcs(reinterpret_cast<const float4*>(arow + 2 * 32));
        float4 av3 = __ldcs(reinterpret_cast<const float4*>(arow + 3 * 32));
        float4 pv0 = __ldcs(reinterpret_cast<const float4*>(prow + 0 * 32));
        float4 pv1 = __ldcs(reinterpret_cast<const float4*>(prow + 1 * 32));
        float4 pv2 = __ldcs(reinterpret_cast<const float4*>(prow + 2 * 32));
        float4 pv3 = __ldcs(reinterpret_cast<const float4*>(prow + 3 * 32));
        float4 nv0 = __ldcs(reinterpret_cast<const float4*>(nrow + 0 * 32));
        float4 nv1 = __ldcs(reinterpret_cast<const float4*>(nrow + 1 * 32));
        float4 nv2 = __ldcs(reinterpret_cast<const float4*>(nrow + 2 * 32));
        float4 nv3 = __ldcs(reinterpret_cast<const float4*>(nrow + 3 * 32));

        float sap, san, d;
        d = av0.x - pv0.x + EPS; sap = d * d;
        d = av0.y - pv0.y + EPS; sap = fmaf(d, d, sap);
        d = av0.z - pv0.z + EPS; sap = fmaf(d, d, sap);
        d = av0.w - pv0.w + EPS; sap = fmaf(d, d, sap);
        d = av1.x - pv1.x + EPS; sap = fmaf(d, d, sap);
        d = av1.y - pv1.y + EPS; sap = fmaf(d, d, sap);
        d = av1.z - pv1.z + EPS; sap = fmaf(d, d, sap);
        d = av1.w - pv1.w + EPS; sap = fmaf(d, d, sap);
        d = av2.x - pv2.x + EPS; sap = fmaf(d, d, sap);
        d = av2.y - pv2.y + EPS; sap = fmaf(d, d, sap);
        d = av2.z - pv2.z + EPS; sap = fmaf(d, d, sap);
        d = av2.w - pv2.w + EPS; sap = fmaf(d, d, sap);
        d = av3.x - pv3.x + EPS; sap = fmaf(d, d, sap);
        d = av3.y - pv3.y + EPS; sap = fmaf(d, d, sap);
        d = av3.z - pv3.z + EPS; sap = fmaf(d, d, sap);
        d = av3.w - pv3.w + EPS; sap = fmaf(d, d, sap);

        d = av0.x - nv0.x + EPS; san = d * d;
        d = av0.y - nv0.y + EPS; san = fmaf(d, d, san);
        d = av0.z - nv0.z + EPS; san = fmaf(d, d, san);
        d = av0.w - nv0.w + EPS; san = fmaf(d, d, san);
        d = av1.x - nv1.x + EPS; san = fmaf(d, d, san);
        d = av1.y - nv1.y + EPS; san = fmaf(d, d, san);
        d = av1.z - nv1.z + EPS; san = fmaf(d, d, san);
        d = av1.w - nv1.w + EPS; san = fmaf(d, d, san);
        d = av2.x - nv2.x + EPS; san = fmaf(d, d, san);
        d = av2.y - nv2.y + EPS; san = fmaf(d, d, san);
        d = av2.z - nv2.z + EPS; san = fmaf(d, d, san);
        d = av2.w - nv2.w + EPS; san = fmaf(d, d, san);
        d = av3.x - nv3.x + EPS; san = fmaf(d, d, san);
        d = av3.y - nv3.y + EPS; san = fmaf(d, d, san);
        d = av3.z - nv3.z + EPS; san = fmaf(d, d, san);
        d = av3.w - nv3.w + EPS; san = fmaf(d, d, san);

        // 3-stage butterfly within each 8-lane group: reduces all 4 rows.
        #pragma unroll
        for (int off = 4; off > 0; off >>= 1) {
            sap += __shfl_xor_sync(0xffffffffu, sap, off);
            san += __shfl_xor_sync(0xffffffffu, san, off);
        }

        if (sub == 0) {
            const int c = cs32[(size_t)myrow * cstride] & 3;
            local += fmaxf(sqrtf(sap) - sqrtf(san) + c_margins[c], 0.0f);
        }
    }

    // Ragged tail (only if B not a multiple of 4, or the last partial group).
    if (rowbase < B) {
        const int myrow = rowbase + grp;
        const bool valid = (myrow < B);
        const size_t rbase = (size_t)(valid ? myrow : 0) * D;
        const float* arow = a + rbase + sub * 4;
        const float* prow = p + rbase + sub * 4;
        const float* nrow = n + rbase + sub * 4;

        float sap = 0.0f, san = 0.0f;
        #pragma unroll
        for (int k = 0; k < 4; k++) {
            float4 av = __ldcs(reinterpret_cast<const float4*>(arow + k * 32));
            float4 pv = __ldcs(reinterpret_cast<const float4*>(prow + k * 32));
            float4 nv = __ldcs(reinterpret_cast<const float4*>(nrow + k * 32));
            float d;
            d = av.x - pv.x + EPS; sap = fmaf(d, d, sap);
            d = av.y - pv.y + EPS; sap = fmaf(d, d, sap);
            d = av.z - pv.z + EPS; sap = fmaf(d, d, sap);
            d = av.w - pv.w + EPS; sap = fmaf(d, d, sap);
            d = av.x - nv.x + EPS; san = fmaf(d, d, san);
            d = av.y - nv.y + EPS; san = fmaf(d, d, san);
            d = av.z - nv.z + EPS; san = fmaf(d, d, san);
            d = av.w - nv.w + EPS; san = fmaf(d, d, san);
        }
        #pragma unroll
        for (int off = 4; off > 0; off >>= 1) {
            sap += __shfl_xor_sync(0xffffffffu, sap, off);
            san += __shfl_xor_sync(0xffffffffu, san, off);
        }
        if (sub == 0 && valid) {
            const int c = cs32[(size_t)myrow * cstride] & 3;
            local += fmaxf(sqrtf(sap) - sqrtf(san) + c_margins[c], 0.0f);
        }
    }

    // ---- Block reduce ----
    #pragma unroll
    for (int off = 16; off > 0; off >>= 1)
        local += __shfl_xor_sync(0xffffffffu, local, off);

    __shared__ float s_part[32];
    if (lane == 0) s_part[warp] = local;
    __syncthreads();

    if (warp == 0) {
        float v = (lane < warps_per_block) ? s_part[lane] : 0.0f;
        #pragma unroll
        for (int off = 16; off > 0; off >>= 1)
            v += __shfl_xor_sync(0xffffffffu, v, off);

        // ---- Fused epilogue: last block writes mean, resets state ----
        if (lane == 0) {
            atomicAdd(&g_sum, (double)v);
            __threadfence();
            const unsigned int old = atomicAdd(&g_count, 1u);
            if (old == gridDim.x - 1u) {
                const double s = atomicAdd(&g_sum, 0.0);  // ordered read
                *out = (float)(s * (double)inv_b);
                g_sum = 0.0;
                g_count = 0u;
                __threadfence();
            }
        }
    }
}

extern "C" void kernel_launch(void* const* d_in, const int* in_sizes, int n_in,
                              void* d_out, int out_size)
{
    const float* anchors = (const float*)d_in[0];
    const float* poss    = (const float*)d_in[1];
    const float* negs    = (const float*)d_in[2];
    const int*   cs32    = (const int*)d_in[3];
    float* out = (float*)d_out;

    const int B = in_sizes[3];
    const int threads = 256;

    // Exactly one occupancy wave: SMs x max-resident-CTAs for this kernel.
    // Host-side queries; no allocation; safe under graph capture. Cached so
    // the grid is identical across capture and replays.
    static int blocks = 0;
    if (blocks == 0) {
        int dev = 0, sms = 0, per_sm = 0;
        cudaGetDevice(&dev);
        cudaDeviceGetAttribute(&sms, cudaDevAttrMultiProcessorCount, dev);
        cudaOccupancyMaxActiveBlocksPerMultiprocessor(
            &per_sm, triplet_fused_kernel, threads, 0);
        if (sms <= 0) sms = 148;
        if (per_sm < 4) per_sm = 4;
        blocks = sms * per_sm;
    }

    triplet_fused_kernel<<<blocks, threads>>>(anchors, poss, negs, cs32, out,
                                              B, 1.0f / (float)B);
}